// round 17
// baseline (speedup 1.0000x reference)
#include <cuda_runtime.h>
#include <cstdint>

#define Bq 16
#define Nq 2048
#define Cq 3
#define Kq 100
#define THREADS 1024
#define NWORD (Nq / 64)      // 32 bitmap words
#define NTILE (Nq / 64)      // 32 tiles; warp w owns tile w
#define KCAP 112
#define NEGV (-1e9f)
#define HSTRIDE 66           // u16 histogram row stride (bank-conflict-free scan)
#define KINV 0x3FFFFFFu      // invalid-entry 26-bit key (sorts last)

// dynamic smem layout (bytes)
#define OFF_KEYSA 0
#define OFF_KEYSB 16384
#define OFF_LOHI  32768
#define OFF_HIST  49152                       // u16[512*66] = 67584
#define OFF_DTOT  (49152 + 67584)             // u32[512]
#define OFF_DBASE (OFF_DTOT + 2048)           // u32[512]
#define SMEM_DYN  (OFF_DBASE + 2048)          // 120832

typedef unsigned long long u64;

// Exactly equivalent to (inter / fmaxf(uni,1e-8f)) > 0.5f for pairs that matter
// (alive boxes have width >= 10 so uni >= 10). Band fallback uses the literal
// reference expression; division rounding (<=0.5ulp) can't cross the band.
__device__ __forceinline__ bool iou_gt_half(float inter, float uni) {
    float h = 0.5f * uni;
    if (inter > h * 1.000002f) return true;
    if (inter < h * 0.999998f) return false;
    return inter / fmaxf(uni, 1e-8f) > 0.5f;
}

__device__ __forceinline__ bool supp_test(float lo, float hi, float wb, float2 p) {
    float inter = fminf(p.y, hi) - fmaxf(p.x, lo);
    float uni   = (p.y - p.x) + wb - inter;
    return (inter > 0.0f) && iou_gt_half(inter, uni);
}

__global__ void __launch_bounds__(THREADS)
roiheads_kernel(const float* __restrict__ logit,   // [B,N,3]
                const float* __restrict__ reg,     // [B,N,6]
                const float* __restrict__ prop,    // [B,N,2]
                const int*   __restrict__ ishape,  // scalar
                float*       __restrict__ out)     // [B,2,K,3]
{
    extern __shared__ unsigned char dynsm[];
    u64*            keysA = (u64*)(dynsm + OFF_KEYSA);
    u64*            keysB = (u64*)(dynsm + OFF_KEYSB);
    float2*         lohi  = (float2*)(dynsm + OFF_LOHI);
    unsigned short* hist  = (unsigned short*)(dynsm + OFF_HIST);
    unsigned*       dtot  = (unsigned*)(dynsm + OFF_DTOT);
    unsigned*       dbase = (unsigned*)(dynsm + OFF_DBASE);

    __shared__ float2 keptLH[KCAP];
    __shared__ u64    alive[NWORD];
    __shared__ int    sDLo, sDHi;
    __shared__ int    sStop, sStopT;
    __shared__ int    wp[NWORD + 1];

    const int b    = blockIdx.x >> 1;
    const int c    = blockIdx.x & 1;
    const int cls  = c + 1;
    const int tid  = threadIdx.x;
    const int lane = tid & 31;
    const int wid  = tid >> 5;           // warp id == owned NMS tile
    const int cbase = tid * 2;           // phase-1 contiguous partition only

    int ib = ishape[0];
    float img = (ib > 0 && ib < (1 << 24)) ? (float)ib : __int_as_float(ib);

    if (tid < NWORD) alive[tid] = 0ull;
    if (tid == 0) { sDLo = 0; sDHi = 0; sStop = 0; sStopT = NTILE - 1; }

    // ---------- Phase 1: softmax + decode + clip + mask -> 26-bit keys ----------
    {
        const float2* lgv = (const float2*)(logit + ((size_t)b * Nq + cbase) * Cq);
        float2 G0 = lgv[0], G1 = lgv[1], G2 = lgv[2];
        const float4  P   = *(const float4*)(prop + ((size_t)b * Nq + cbase) * 2);
        float lg[6] = {G0.x, G0.y, G1.x, G1.y, G2.x, G2.y};
        float pr[4] = {P.x, P.y, P.z, P.w};

        #pragma unroll
        for (int r = 0; r < 2; r++) {
            int j = cbase + r;
            float l0 = lg[r*3+0], l1 = lg[r*3+1], l2 = lg[r*3+2];
            float m  = fmaxf(l0, fmaxf(l1, l2));
            float e0 = expf(l0 - m), e1 = expf(l1 - m), e2 = expf(l2 - m);
            float s  = ((cls == 1) ? e1 : e2) / (e0 + e1 + e2);

            const float2 dd = *(const float2*)(reg + ((size_t)b * Nq + j) * (2 * Cq) + 2 * cls);
            float dx = dd.x;
            float dw = fminf(dd.y, 4.0f);

            float p0 = pr[r*2+0], p1 = pr[r*2+1];
            float w   = p1 - p0;
            float ctr = p0 + 0.5f * w;
            float pc  = dx * w + ctr;
            float pw  = expf(dw) * w;
            float lo  = fminf(fmaxf(pc - 0.5f * pw, 0.0f), img);
            float hi  = fminf(fmaxf(pc + 0.5f * pw, 0.0f), img);

            bool valid = ((hi - lo) >= 10.0f) && (s >= 0.05f);
            // 26-bit descending-score key: valid s in [0.05, 1) maps to
            // [1, 0x2333333] ascending-with-descending-score; invalid -> max.
            unsigned k26 = valid ? (0x3F800000u - __float_as_uint(s)) : KINV;

            lohi[j]  = make_float2(lo, hi);
            keysA[j] = ((u64)k26 << 32) | (unsigned)j;
        }
    }
    __syncthreads();

    // ---------- Phase 2: stable LSD radix sort, 3 passes (9/9/8 bits) ----------
    {
        u64* src = keysA;
        u64* dst = keysB;
        const unsigned lt = (1u << lane) - 1u;
        const int SH[3] = {32, 41, 50};
        const unsigned MK[3] = {0x1FFu, 0x1FFu, 0xFFu};
        const int NB[3] = {512, 512, 256};
        #pragma unroll
        for (int p = 0; p < 3; p++) {
            const int sh = SH[p];
            const unsigned mk = MK[p];
            const int nbin = NB[p];
            for (int i = tid; i < nbin * (HSTRIDE / 2); i += THREADS)
                ((unsigned*)hist)[i] = 0;   // zero u16[nbin*66] as u32 pairs
            __syncthreads();

            u64 k0 = src[tid];
            u64 k1 = src[tid + 1024];
            unsigned d0 = (unsigned)(k0 >> sh) & mk;
            unsigned d1 = (unsigned)(k1 >> sh) & mk;
            unsigned m0 = __match_any_sync(0xffffffffu, d0);
            unsigned m1 = __match_any_sync(0xffffffffu, d1);
            if (__ffs(m0) - 1 == lane)
                hist[d0 * HSTRIDE + wid]      = (unsigned short)__popc(m0);
            if (__ffs(m1) - 1 == lane)
                hist[d1 * HSTRIDE + 32 + wid] = (unsigned short)__popc(m1);
            __syncthreads();

            if (tid < nbin) {          // per-digit exclusive row prefix (in place)
                unsigned short* h = hist + tid * HSTRIDE;
                unsigned sum = 0;
                #pragma unroll
                for (int i = 0; i < 64; i++) {
                    unsigned t = h[i];
                    h[i] = (unsigned short)sum;
                    sum += t;
                }
                dtot[tid] = sum;
            }
            __syncthreads();

            if (tid < 32) {            // exclusive scan of nbin digit totals
                const int G = nbin / 32;   // 16 or 8 digits per lane
                unsigned tg[16], run = 0;
                for (int i = 0; i < G; i++) tg[i] = dtot[tid * G + i];
                for (int i = 0; i < G; i++) { unsigned u = tg[i]; tg[i] = run; run += u; }
                unsigned inc = run;
                #pragma unroll
                for (int d = 1; d < 32; d <<= 1) {
                    unsigned x = __shfl_up_sync(0xffffffffu, inc, d);
                    if (lane >= d) inc += x;
                }
                unsigned excl = inc - run;
                for (int i = 0; i < G; i++) dbase[tid * G + i] = excl + tg[i];
            }
            __syncthreads();

            dst[dbase[d0] + hist[d0 * HSTRIDE + wid]      + __popc(m0 & lt)] = k0;
            dst[dbase[d1] + hist[d1 * HSTRIDE + 32 + wid] + __popc(m1 & lt)] = k1;
            __syncthreads();

            u64* tmp = src; src = dst; dst = tmp;   // 3 passes: data ends in keysB
        }
    }
    u64* sorted = keysB;

    // ---------- Phase 3: cache owned boxes (strided in tile); alive bitmap ----------
    // Thread owns sorted positions wid*64 + lane + 32*r (r=0,1): warp-local
    // layout matches the greedy's {L, L+32} ballot mapping.
    u64 myKey[2];
    float myLo[2], myHi[2];
    unsigned myAlive = 0;
    #pragma unroll
    for (int r = 0; r < 2; r++) {
        int pos = wid * 64 + lane + 32 * r;
        u64 key = sorted[pos];
        myKey[r] = key;
        float2 lh = lohi[(int)(key & 0xffffffffu)];
        myLo[r] = lh.x;
        myHi[r] = lh.y;
        if ((unsigned)(key >> 32) != KINV)
            myAlive |= (1u << r);
    }
    if (myAlive)
        atomicOr(&alive[wid], ((u64)(myAlive & 1u) << lane)
                            | ((u64)((myAlive >> 1) & 1u) << (lane + 32)));
    __syncthreads();

    // ---------- Phase 4: rotating-greedy tile NMS with dead-round skipping ----------
    int kt = 0;
    int dLo = 0, dHi = 0;

    for (int t = 0; t < NTILE; t++) {
        u64 at = alive[t];
        if (at == 0ull && dHi <= dLo) continue;   // dead round: no work, no writes

        if (wid == t) {
            // greedy warp: tile boxes already in registers, zero LDS for boxes
            const float glo0 = myLo[0], ghi0 = myHi[0];
            const float glo1 = myLo[1], ghi1 = myHi[1];
            const float w0 = ghi0 - glo0, w1 = ghi1 - glo1;
            const u64 pk0 = ((u64)__float_as_uint(ghi0) << 32) | __float_as_uint(glo0);
            const u64 pk1 = ((u64)__float_as_uint(ghi1) << 32) | __float_as_uint(glo1);

            // urgent: apply previous round's kept delta (register boxes)
            if (at != 0ull && dHi > dLo) {
                bool q0 = false, q1 = false;
                for (int s = dLo; s < dHi; s++) {
                    float2 p = keptLH[s];
                    q0 |= supp_test(glo0, ghi0, w0, p);
                    q1 |= supp_test(glo1, ghi1, w1, p);
                }
                unsigned b0 = __ballot_sync(0xffffffffu, q0);
                unsigned b1 = __ballot_sync(0xffffffffu, q1);
                at &= ~(((u64)b1 << 32) | (u64)b0);
            }

            // greedy over the tile, capped at Kq kept total
            const int T0 = kt;
            u64 kept = 0;
            while (at && kt < Kq) {
                int pos = __ffsll((long long)at) - 1;
                kept |= (1ull << pos);
                u64 got = __shfl_sync(0xffffffffu, (pos & 32) ? pk1 : pk0, pos & 31);
                float pl = __uint_as_float((unsigned)(got & 0xffffffffu));
                float ph = __uint_as_float((unsigned)(got >> 32));
                float pw = ph - pl;
                bool q0 = false, q1 = false;
                {
                    float inter = fminf(ph, ghi0) - fmaxf(pl, glo0);
                    if (inter > 0.0f) q0 = iou_gt_half(inter, pw + w0 - inter);
                    inter = fminf(ph, ghi1) - fmaxf(pl, glo1);
                    if (inter > 0.0f) q1 = iou_gt_half(inter, pw + w1 - inter);
                }
                unsigned b0 = __ballot_sync(0xffffffffu, q0);
                unsigned b1 = __ballot_sync(0xffffffffu, q1);
                at &= ~(((u64)b1 << 32) | (u64)b0);
                at = (pos < 63) ? (at & (~0ull << (pos + 1))) : 0ull;
                if (lane == 0) keptLH[kt] = make_float2(pl, ph);
                kt++;
            }
            if (lane == 0) {
                alive[t] = kept;
                sDLo = T0;
                sDHi = kt;
                if (kt >= Kq) { sStop = 1; sStopT = t; }
            }
        } else if (wid > t && myAlive && dHi > dLo) {
            // background: apply current delta to my (still-pending) tile boxes
            unsigned killed = 0;
            #pragma unroll
            for (int r = 0; r < 2; r++) {
                if (myAlive & (1u << r)) {
                    float lo = myLo[r], hi = myHi[r];
                    float wb = hi - lo;
                    for (int s = dLo; s < dHi; s++) {
                        float2 p = keptLH[s];
                        if (supp_test(lo, hi, wb, p)) { killed |= (1u << r); break; }
                    }
                }
            }
            if (killed) {
                myAlive &= ~killed;
                atomicAnd(&alive[wid], ~(((u64)(killed & 1u) << lane)
                                       | ((u64)((killed >> 1) & 1u) << (lane + 32))));
            }
        }
        __syncthreads();
        if (sStop) break;
        dLo = sDLo;
        dHi = sDHi;
    }

    if (tid < NWORD && tid > sStopT) alive[tid] = 0ull;
    __syncthreads();

    // ---------- Phase 5: ranks + emit top-K with NEG padding ----------
    if (tid == 0) {
        int acc = 0;
        #pragma unroll
        for (int w = 0; w < NWORD; w++) { wp[w] = acc; acc += __popcll(alive[w]); }
        wp[NWORD] = acc;
    }
    __syncthreads();
    const int T = wp[NWORD];
    float* o = out + ((size_t)(b * 2 + c)) * Kq * 3;

    const u64 aw = alive[wid];
    #pragma unroll
    for (int r = 0; r < 2; r++) {
        int bit = lane + 32 * r;
        int p   = wid * 64 + bit;
        u64 lowmask = (bit == 0) ? 0ull : ((1ull << bit) - 1ull);
        int  kr   = wp[wid] + __popcll(aw & lowmask);
        bool kept = (aw >> bit) & 1ull;
        if (kept) {
            if (kr < Kq) {
                o[kr * 3 + 0] = myLo[r];
                o[kr * 3 + 1] = myHi[r];
                // exact score recovery from the 26-bit key (kept => valid)
                o[kr * 3 + 2] = __uint_as_float(0x3F800000u - (unsigned)(myKey[r] >> 32));
            }
        } else {
            int nr = p - kr;
            if (T < Kq && nr < Kq - T) {
                int slot = T + nr;
                o[slot * 3 + 0] = myLo[r];
                o[slot * 3 + 1] = myHi[r];
                o[slot * 3 + 2] = NEGV;
            }
        }
    }
}

extern "C" void kernel_launch(void* const* d_in, const int* in_sizes, int n_in,
                              void* d_out, int out_size)
{
    const float* logit  = (const float*)d_in[0];   // [16,2048,3]
    const float* reg    = (const float*)d_in[1];   // [16,2048,6]
    const float* prop   = (const float*)d_in[2];   // [16,2048,2]
    const int*   ishape = (const int*)d_in[3];     // scalar
    float* out = (float*)d_out;                    // [16,2,100,3]

    cudaFuncSetAttribute(roiheads_kernel,
                         cudaFuncAttributeMaxDynamicSharedMemorySize, SMEM_DYN);
    roiheads_kernel<<<Bq * (Cq - 1), THREADS, SMEM_DYN>>>(logit, reg, prop, ishape, out);
}